// round 2
// baseline (speedup 1.0000x reference)
#include <cuda_runtime.h>
#include <cstdint>

#define IN_F   4096
#define OUT_F  4096
#define MROWS  8192          // B*S = 4*2048

#define BM 128
#define BN 128
#define BK 32
#define PITCH 36             // floats per smem row: conflict-free + 16B-aligned
#define STAGES 4
#define KTILES (IN_F / BK)   // 128
#define TILE_FLOATS (BM * PITCH)                 // 4608 floats per tile
#define SMEM_FLOATS (2 * STAGES * TILE_FLOATS)   // A + B, 4 stages
#define SMEM_BYTES  (SMEM_FLOATS * 4)            // 147456

// ---------------- scratch: dequantized W (no runtime allocation allowed) ----
__device__ __align__(1024) float g_wdeq[(size_t)OUT_F * IN_F];   // 64 MB

// ---------------- helpers ----------------
__device__ __forceinline__ uint32_t s2u(const void* p) {
    uint32_t a;
    asm("{ .reg .u64 t; cvta.to.shared.u64 t, %1; cvt.u32.u64 %0, t; }" : "=r"(a) : "l"(p));
    return a;
}
__device__ __forceinline__ void cp_async16(uint32_t saddr, const void* gaddr) {
    asm volatile("cp.async.cg.shared.global [%0], [%1], 16;" :: "r"(saddr), "l"(gaddr) : "memory");
}
__device__ __forceinline__ void cp_commit() {
    asm volatile("cp.async.commit_group;" ::: "memory");
}
template <int N>
__device__ __forceinline__ void cp_wait() {
    asm volatile("cp.async.wait_group %0;" :: "n"(N) : "memory");
}
__device__ __forceinline__ uint32_t f2tf32u(float v) {
    uint32_t r;
    asm("cvt.rna.tf32.f32 %0, %1;" : "=r"(r) : "f"(v));
    return r;
}
__device__ __forceinline__ void mma_tf32(float* d, const uint32_t* a, const uint32_t* b) {
    asm volatile(
        "mma.sync.aligned.m16n8k8.row.col.f32.tf32.tf32.f32 "
        "{%0,%1,%2,%3}, {%4,%5,%6,%7}, {%8,%9}, {%0,%1,%2,%3};"
        : "+f"(d[0]), "+f"(d[1]), "+f"(d[2]), "+f"(d[3])
        : "r"(a[0]), "r"(a[1]), "r"(a[2]), "r"(a[3]), "r"(b[0]), "r"(b[1]));
}

// ---------------- kernel 1: dequantize W (gather + tf32 round) --------------
__global__ void __launch_bounds__(256) wdeq_kernel(const float* __restrict__ cent,
                                                   const int* __restrict__ idx,
                                                   float* __restrict__ w) {
    __shared__ float c[256];
    int t = threadIdx.x;
    c[t] = __uint_as_float(f2tf32u(cent[t]));
    __syncthreads();
    size_t i = ((size_t)blockIdx.x * 256 + t) * 4;
    int4 v = *reinterpret_cast<const int4*>(idx + i);
    float4 o = make_float4(c[v.x], c[v.y], c[v.z], c[v.w]);
    *reinterpret_cast<float4*>(w + i) = o;
}

// ---------------- kernel 2: pipelined tf32 mma.sync GEMM --------------------
// out[m,n] = sum_k X[m,k] * W[n,k];  X: [8192,4096], W(dequant): [4096,4096]
__global__ void __launch_bounds__(256, 1)
gemm_tf32(const float* __restrict__ X, const float* __restrict__ W,
          float* __restrict__ out) {
    extern __shared__ float smem[];
    float* As = smem;                         // [STAGES][BM][PITCH]
    float* Bs = smem + STAGES * TILE_FLOATS;  // [STAGES][BN][PITCH]
    const uint32_t As_u = s2u(As);
    const uint32_t Bs_u = s2u(Bs);

    const int tid = threadIdx.x;
    const int wid = tid >> 5, lane = tid & 31;
    const int warp_m = wid >> 2;      // 0..1  -> 64 rows each
    const int warp_n = wid & 3;       // 0..3  -> 32 cols each

    // grid swizzle: GROUP_M = 8 M-tiles per supertile column for L2 reuse of W
    const int NT = OUT_F / BN;        // 32
    const int GM = 8;
    int bid = blockIdx.x;
    int grp = bid / (GM * NT);
    int inb = bid % (GM * NT);
    int m_tile = grp * GM + (inb % GM);
    int n_tile = inb / GM;
    const int m_base = m_tile * BM;
    const int n_base = n_tile * BN;

    // cooperative load mapping: 4 iters x 256 thr cover 128 rows x 8 float4
    const int ld_row0 = tid >> 3;           // +64 per iter... (see loop)
    const int ld_c4   = (tid & 7) * 4;

    float acc[4][4][4];
    #pragma unroll
    for (int mi = 0; mi < 4; mi++)
        #pragma unroll
        for (int ni = 0; ni < 4; ni++)
            #pragma unroll
            for (int e = 0; e < 4; e++) acc[mi][ni][e] = 0.f;

    auto load_tile = [&](int kt, int s) {
        const float* ga = X + (size_t)(m_base + ld_row0) * IN_F + kt * BK + ld_c4;
        const float* gb = W + (size_t)(n_base + ld_row0) * IN_F + kt * BK + ld_c4;
        uint32_t sa = As_u + (uint32_t)(s * TILE_FLOATS + ld_row0 * PITCH + ld_c4) * 4;
        uint32_t sb = Bs_u + (uint32_t)(s * TILE_FLOATS + ld_row0 * PITCH + ld_c4) * 4;
        #pragma unroll
        for (int i = 0; i < 4; i++) {
            cp_async16(sa, ga);
            cp_async16(sb, gb);
            ga += 32 * IN_F;   gb += 32 * IN_F;
            sa += 32 * PITCH * 4;  sb += 32 * PITCH * 4;
        }
        cp_commit();
    };

    // prologue: fill STAGES-1 = 3 stages
    load_tile(0, 0);
    load_tile(1, 1);
    load_tile(2, 2);

    const int a_r0 = warp_m * 64 + (lane >> 2);   // + mi*16 (+8)
    const int b_c0 = warp_n * 32 + (lane >> 2);   // + ni*8
    const int k_l  = lane & 3;

    for (int kt = 0; kt < KTILES; kt++) {
        if (kt < KTILES - 3) cp_wait<2>(); else cp_wait<0>();
        __syncthreads();
        if (kt + 3 < KTILES) load_tile(kt + 3, (kt + 3) & 3);

        const float* A0 = As + (kt & 3) * TILE_FLOATS;
        const float* B0 = Bs + (kt & 3) * TILE_FLOATS;

        #pragma unroll
        for (int k0 = 0; k0 < BK; k0 += 8) {
            uint32_t a[4][4], b[4][2];
            #pragma unroll
            for (int mi = 0; mi < 4; mi++) {
                const float* ap = A0 + (a_r0 + mi * 16) * PITCH + k0 + k_l;
                a[mi][0] = f2tf32u(ap[0]);
                a[mi][1] = f2tf32u(ap[8 * PITCH]);
                a[mi][2] = f2tf32u(ap[4]);
                a[mi][3] = f2tf32u(ap[8 * PITCH + 4]);
            }
            #pragma unroll
            for (int ni = 0; ni < 4; ni++) {
                const float* bp = B0 + (b_c0 + ni * 8) * PITCH + k0 + k_l;
                b[ni][0] = __float_as_uint(bp[0]);   // W pre-rounded to tf32
                b[ni][1] = __float_as_uint(bp[4]);
            }
            #pragma unroll
            for (int mi = 0; mi < 4; mi++)
                #pragma unroll
                for (int ni = 0; ni < 4; ni++)
                    mma_tf32(acc[mi][ni], a[mi], b[ni]);
        }
        __syncthreads();
    }

    // epilogue: direct STG.64 (2 consecutive floats per store)
    #pragma unroll
    for (int mi = 0; mi < 4; mi++) {
        int r0 = m_base + warp_m * 64 + mi * 16 + (lane >> 2);
        #pragma unroll
        for (int ni = 0; ni < 4; ni++) {
            int c = n_base + warp_n * 32 + ni * 8 + 2 * (lane & 3);
            float2 v0 = make_float2(acc[mi][ni][0], acc[mi][ni][1]);
            float2 v1 = make_float2(acc[mi][ni][2], acc[mi][ni][3]);
            *reinterpret_cast<float2*>(out + (size_t)r0 * OUT_F + c) = v0;
            *reinterpret_cast<float2*>(out + (size_t)(r0 + 8) * OUT_F + c) = v1;
        }
    }
}

// ---------------- host ----------------
extern "C" void kernel_launch(void* const* d_in, const int* in_sizes, int n_in,
                              void* d_out, int out_size) {
    const float* x    = (const float*)d_in[0];   // [8192, 4096] fp32
    const float* cent = (const float*)d_in[1];   // [256, 1] fp32
    const int*   idx  = (const int*)d_in[2];     // [4096, 4096] int32
    float* out = (float*)d_out;                  // [8192, 4096] fp32

    void* wdeq_ptr = nullptr;
    cudaGetSymbolAddress(&wdeq_ptr, g_wdeq);

    wdeq_kernel<<<(size_t)OUT_F * IN_F / 1024, 256>>>(cent, idx, (float*)wdeq_ptr);

    static_assert(SMEM_BYTES == 147456, "smem size");
    cudaFuncSetAttribute(gemm_tf32, cudaFuncAttributeMaxDynamicSharedMemorySize, SMEM_BYTES);
    int grid = (MROWS / BM) * (OUT_F / BN);   // 64 * 32 = 2048
    gemm_tf32<<<grid, 256, SMEM_BYTES>>>(x, (const float*)wdeq_ptr, out);
}

// round 4
// speedup vs baseline: 1.3814x; 1.3814x over previous
#include <cuda_runtime.h>
#include <cstdint>

#define IN_F   4096
#define OUT_F  4096
#define MROWS  8192          // B*S = 4*2048

#define BM 128
#define BN 128
#define BK 32
#define PITCH 36             // floats per smem row: conflict-free + 16B-aligned
#define STAGES 3
#define KTILES (IN_F / BK)   // 128
#define TILE_FLOATS (BM * PITCH)                 // 4608 floats per tile
#define SMEM_BYTES  (2 * STAGES * TILE_FLOATS * 4)   // 110592

// ---------------- scratch (no runtime allocation allowed) -------------------
__device__ __align__(1024) float g_wdeq[(size_t)OUT_F * IN_F];   // 64 MB, tf32-rounded W
__device__ __align__(1024) float g_xcvt[(size_t)MROWS * IN_F];   // 128 MB, tf32-rounded X

// ---------------- helpers ----------------
__device__ __forceinline__ uint32_t s2u(const void* p) {
    uint32_t a;
    asm("{ .reg .u64 t; cvta.to.shared.u64 t, %1; cvt.u32.u64 %0, t; }" : "=r"(a) : "l"(p));
    return a;
}
__device__ __forceinline__ void cp_async16(uint32_t saddr, const void* gaddr) {
    asm volatile("cp.async.cg.shared.global [%0], [%1], 16;" :: "r"(saddr), "l"(gaddr) : "memory");
}
__device__ __forceinline__ void cp_commit() {
    asm volatile("cp.async.commit_group;" ::: "memory");
}
template <int N>
__device__ __forceinline__ void cp_wait() {
    asm volatile("cp.async.wait_group %0;" :: "n"(N) : "memory");
}
__device__ __forceinline__ uint32_t f2tf32u(float v) {
    uint32_t r;
    asm("cvt.rna.tf32.f32 %0, %1;" : "=r"(r) : "f"(v));
    return r;
}
__device__ __forceinline__ void ldsm_x4(uint32_t* r, uint32_t addr) {
    asm volatile("ldmatrix.sync.aligned.m8n8.x4.shared.b16 {%0,%1,%2,%3}, [%4];"
                 : "=r"(r[0]), "=r"(r[1]), "=r"(r[2]), "=r"(r[3]) : "r"(addr));
}
__device__ __forceinline__ void mma_tf32(float* d, const uint32_t* a, const uint32_t* b) {
    asm volatile(
        "mma.sync.aligned.m16n8k8.row.col.f32.tf32.tf32.f32 "
        "{%0,%1,%2,%3}, {%4,%5,%6,%7}, {%8,%9}, {%0,%1,%2,%3};"
        : "+f"(d[0]), "+f"(d[1]), "+f"(d[2]), "+f"(d[3])
        : "r"(a[0]), "r"(a[1]), "r"(a[2]), "r"(a[3]), "r"(b[0]), "r"(b[1]));
}

// ---------------- kernel 1: dequantize W (gather + tf32 round) --------------
__global__ void __launch_bounds__(256) wdeq_kernel(const float* __restrict__ cent,
                                                   const int* __restrict__ idx,
                                                   float* __restrict__ w) {
    __shared__ float c[256];
    int t = threadIdx.x;
    c[t] = __uint_as_float(f2tf32u(cent[t]));
    __syncthreads();
    size_t i = ((size_t)blockIdx.x * 256 + t) * 4;
    int4 v = *reinterpret_cast<const int4*>(idx + i);
    float4 o = make_float4(c[v.x], c[v.y], c[v.z], c[v.w]);
    *reinterpret_cast<float4*>(w + i) = o;
}

// ---------------- kernel 2: round X to tf32 ---------------------------------
__global__ void __launch_bounds__(256) xcvt_kernel(const float* __restrict__ x,
                                                   float* __restrict__ y) {
    size_t i = ((size_t)blockIdx.x * 256 + threadIdx.x) * 4;
    float4 v = *reinterpret_cast<const float4*>(x + i);
    uint4 o;
    o.x = f2tf32u(v.x); o.y = f2tf32u(v.y); o.z = f2tf32u(v.z); o.w = f2tf32u(v.w);
    *reinterpret_cast<uint4*>(y + i) = o;
}

// ---------------- kernel 3: pipelined tf32 mma.sync GEMM (ldmatrix) ---------
// out[m,n] = sum_k X[m,k] * W[n,k]
__global__ void __launch_bounds__(256, 2)
gemm_tf32(const float* __restrict__ X, const float* __restrict__ W,
          float* __restrict__ out) {
    extern __shared__ float smem[];
    float* As = smem;                         // [STAGES][BM][PITCH]
    float* Bs = smem + STAGES * TILE_FLOATS;  // [STAGES][BN][PITCH]
    const uint32_t As_u = s2u(As);
    const uint32_t Bs_u = s2u(Bs);

    const int tid = threadIdx.x;
    const int wid = tid >> 5, lane = tid & 31;
    const int warp_m = wid >> 2;      // 0..1  -> 64 rows each
    const int warp_n = wid & 3;       // 0..3  -> 32 cols each

    // grid swizzle: 8 M-tiles per supertile column for L2 reuse of W
    const int NT = OUT_F / BN;        // 32
    const int GM = 8;
    int bid = blockIdx.x;
    int grp = bid / (GM * NT);
    int inb = bid % (GM * NT);
    int m_tile = grp * GM + (inb % GM);
    int n_tile = inb / GM;
    const int m_base = m_tile * BM;
    const int n_base = n_tile * BN;

    // cooperative gmem->smem mapping: 4 iters x 256 thr cover 128 rows x 8 float4
    const int ld_row0 = tid >> 3;
    const int ld_c4   = (tid & 7) * 4;

    // ldmatrix per-thread base byte offsets (within a stage)
    const int l7 = lane & 7;
    const uint32_t a_base = As_u +
        (uint32_t)((warp_m * 64 + l7 + ((lane >> 3) & 1) * 8) * PITCH + (lane >> 4) * 4) * 4;
    const uint32_t b_base = Bs_u +
        (uint32_t)((warp_n * 32 + l7 + (lane >> 4) * 8) * PITCH + ((lane >> 3) & 1) * 4) * 4;

    float acc[4][4][4];
    #pragma unroll
    for (int mi = 0; mi < 4; mi++)
        #pragma unroll
        for (int ni = 0; ni < 4; ni++)
            #pragma unroll
            for (int e = 0; e < 4; e++) acc[mi][ni][e] = 0.f;

    auto load_tile = [&](int kt, int s) {
        const float* ga = X + (size_t)(m_base + ld_row0) * IN_F + kt * BK + ld_c4;
        const float* gb = W + (size_t)(n_base + ld_row0) * IN_F + kt * BK + ld_c4;
        uint32_t sa = As_u + (uint32_t)(s * TILE_FLOATS + ld_row0 * PITCH + ld_c4) * 4;
        uint32_t sb = Bs_u + (uint32_t)(s * TILE_FLOATS + ld_row0 * PITCH + ld_c4) * 4;
        #pragma unroll
        for (int i = 0; i < 4; i++) {
            cp_async16(sa, ga);
            cp_async16(sb, gb);
            ga += 32 * IN_F;   gb += 32 * IN_F;
            sa += 32 * PITCH * 4;  sb += 32 * PITCH * 4;
        }
        cp_commit();
    };

    // prologue: fill 2 of 3 stages
    load_tile(0, 0);
    load_tile(1, 1);

    int sc = 0;   // compute stage
    for (int kt = 0; kt < KTILES; kt++) {
        if (kt + 1 < KTILES) cp_wait<1>(); else cp_wait<0>();
        __syncthreads();
        if (kt + 2 < KTILES) {
            int sl = sc + 2; if (sl >= STAGES) sl -= STAGES;
            load_tile(kt + 2, sl);
        }

        const uint32_t st_off = (uint32_t)(sc * TILE_FLOATS * 4);
        #pragma unroll
        for (int k0 = 0; k0 < BK; k0 += 8) {
            uint32_t a[4][4], b[2][4];
            #pragma unroll
            for (int mi = 0; mi < 4; mi++)
                ldsm_x4(a[mi], a_base + st_off + (uint32_t)(k0 * 4 + mi * 16 * PITCH * 4));
            ldsm_x4(b[0], b_base + st_off + (uint32_t)(k0 * 4));
            ldsm_x4(b[1], b_base + st_off + (uint32_t)(k0 * 4 + 16 * PITCH * 4));
            #pragma unroll
            for (int mi = 0; mi < 4; mi++) {
                mma_tf32(acc[mi][0], a[mi], &b[0][0]);
                mma_tf32(acc[mi][1], a[mi], &b[0][2]);
                mma_tf32(acc[mi][2], a[mi], &b[1][0]);
                mma_tf32(acc[mi][3], a[mi], &b[1][2]);
            }
        }
        sc = (sc + 1 == STAGES) ? 0 : sc + 1;
    }

    // epilogue: direct STG.64
    #pragma unroll
    for (int mi = 0; mi < 4; mi++) {
        int r0 = m_base + warp_m * 64 + mi * 16 + (lane >> 2);
        #pragma unroll
        for (int ni = 0; ni < 4; ni++) {
            int c = n_base + warp_n * 32 + ni * 8 + 2 * (lane & 3);
            float2 v0 = make_float2(acc[mi][ni][0], acc[mi][ni][1]);
            float2 v1 = make_float2(acc[mi][ni][2], acc[mi][ni][3]);
            *reinterpret_cast<float2*>(out + (size_t)r0 * OUT_F + c) = v0;
            *reinterpret_cast<float2*>(out + (size_t)(r0 + 8) * OUT_F + c) = v1;
        }
    }
}

// ---------------- host ----------------
extern "C" void kernel_launch(void* const* d_in, const int* in_sizes, int n_in,
                              void* d_out, int out_size) {
    const float* x    = (const float*)d_in[0];   // [8192, 4096] fp32
    const float* cent = (const float*)d_in[1];   // [256, 1] fp32
    const int*   idx  = (const int*)d_in[2];     // [4096, 4096] int32
    float* out = (float*)d_out;                  // [8192, 4096] fp32

    void* wdeq_ptr = nullptr; cudaGetSymbolAddress(&wdeq_ptr, g_wdeq);
    void* xcvt_ptr = nullptr; cudaGetSymbolAddress(&xcvt_ptr, g_xcvt);

    wdeq_kernel<<<(size_t)OUT_F * IN_F / 1024, 256>>>(cent, idx, (float*)wdeq_ptr);
    xcvt_kernel<<<(size_t)MROWS * IN_F / 1024, 256>>>(x, (float*)xcvt_ptr);

    cudaFuncSetAttribute(gemm_tf32, cudaFuncAttributeMaxDynamicSharedMemorySize, SMEM_BYTES);
    int grid = (MROWS / BM) * (OUT_F / BN);   // 64 * 32 = 2048
    gemm_tf32<<<grid, 256, SMEM_BYTES>>>((const float*)xcvt_ptr, (const float*)wdeq_ptr, out);
}

// round 5
// speedup vs baseline: 2.6811x; 1.9409x over previous
#include <cuda_runtime.h>
#include <cuda_fp16.h>
#include <cstdint>

#define IN_F   4096
#define OUT_F  4096
#define MROWS  8192          // B*S = 4*2048

#define BM 128
#define BN 128
#define BK 64                // halves per k-tile
#define PITCH 72             // halves per smem row (144 B): ldmatrix conflict-free
#define STAGES 3
#define KTILES (IN_F / BK)   // 64
#define TILE_HALves (BM * PITCH)                      // 9216 halves
#define SMEM_BYTES  (2 * STAGES * TILE_HALves * 2)    // 110592

// ---------------- scratch (no runtime allocation allowed) -------------------
__device__ __align__(1024) __half g_w16[(size_t)OUT_F * IN_F];   // 32 MB
__device__ __align__(1024) __half g_x16[(size_t)MROWS * IN_F];   // 64 MB

// ---------------- helpers ----------------
__device__ __forceinline__ uint32_t s2u(const void* p) {
    uint32_t a;
    asm("{ .reg .u64 t; cvta.to.shared.u64 t, %1; cvt.u32.u64 %0, t; }" : "=r"(a) : "l"(p));
    return a;
}
__device__ __forceinline__ void cp_async16(uint32_t saddr, const void* gaddr) {
    asm volatile("cp.async.cg.shared.global [%0], [%1], 16;" :: "r"(saddr), "l"(gaddr) : "memory");
}
__device__ __forceinline__ void cp_commit() {
    asm volatile("cp.async.commit_group;" ::: "memory");
}
template <int N>
__device__ __forceinline__ void cp_wait() {
    asm volatile("cp.async.wait_group %0;" :: "n"(N) : "memory");
}
__device__ __forceinline__ void ldsm_x4(uint32_t* r, uint32_t addr) {
    asm volatile("ldmatrix.sync.aligned.m8n8.x4.shared.b16 {%0,%1,%2,%3}, [%4];"
                 : "=r"(r[0]), "=r"(r[1]), "=r"(r[2]), "=r"(r[3]) : "r"(addr));
}
__device__ __forceinline__ void mma_f16(float* d, const uint32_t* a, const uint32_t* b) {
    asm volatile(
        "mma.sync.aligned.m16n8k16.row.col.f32.f16.f16.f32 "
        "{%0,%1,%2,%3}, {%4,%5,%6,%7}, {%8,%9}, {%0,%1,%2,%3};"
        : "+f"(d[0]), "+f"(d[1]), "+f"(d[2]), "+f"(d[3])
        : "r"(a[0]), "r"(a[1]), "r"(a[2]), "r"(a[3]), "r"(b[0]), "r"(b[1]));
}

// ---------------- kernel 1: dequantize W -> fp16 ----------------------------
__global__ void __launch_bounds__(256) wdeq_kernel(const float* __restrict__ cent,
                                                   const int* __restrict__ idx,
                                                   __half* __restrict__ w) {
    __shared__ __half c[256];
    int t = threadIdx.x;
    c[t] = __float2half_rn(cent[t]);
    __syncthreads();
    size_t i = ((size_t)blockIdx.x * 256 + t) * 8;
    int4 v0 = *reinterpret_cast<const int4*>(idx + i);
    int4 v1 = *reinterpret_cast<const int4*>(idx + i + 4);
    __half h[8];
    h[0] = c[v0.x]; h[1] = c[v0.y]; h[2] = c[v0.z]; h[3] = c[v0.w];
    h[4] = c[v1.x]; h[5] = c[v1.y]; h[6] = c[v1.z]; h[7] = c[v1.w];
    *reinterpret_cast<uint4*>(w + i) = *reinterpret_cast<uint4*>(h);
}

// ---------------- kernel 2: X fp32 -> fp16 ----------------------------------
__global__ void __launch_bounds__(256) xcvt_kernel(const float* __restrict__ x,
                                                   __half* __restrict__ y) {
    size_t i = ((size_t)blockIdx.x * 256 + threadIdx.x) * 8;
    float4 v0 = *reinterpret_cast<const float4*>(x + i);
    float4 v1 = *reinterpret_cast<const float4*>(x + i + 4);
    __half h[8];
    h[0] = __float2half_rn(v0.x); h[1] = __float2half_rn(v0.y);
    h[2] = __float2half_rn(v0.z); h[3] = __float2half_rn(v0.w);
    h[4] = __float2half_rn(v1.x); h[5] = __float2half_rn(v1.y);
    h[6] = __float2half_rn(v1.z); h[7] = __float2half_rn(v1.w);
    *reinterpret_cast<uint4*>(y + i) = *reinterpret_cast<uint4*>(h);
}

// ---------------- kernel 3: pipelined fp16 mma.sync GEMM --------------------
// out[m,n] = sum_k X[m,k] * W[n,k]
__global__ void __launch_bounds__(256, 2)
gemm_f16(const __half* __restrict__ X, const __half* __restrict__ W,
         float* __restrict__ out) {
    extern __shared__ __half smem[];
    __half* As = smem;                          // [STAGES][BM][PITCH]
    __half* Bs = smem + STAGES * TILE_HALves;   // [STAGES][BN][PITCH]
    const uint32_t As_u = s2u(As);
    const uint32_t Bs_u = s2u(Bs);

    const int tid = threadIdx.x;
    const int wid = tid >> 5, lane = tid & 31;
    const int warp_m = wid >> 2;      // 0..1 -> 64 rows
    const int warp_n = wid & 3;       // 0..3 -> 32 cols

    // grid swizzle: 8 M-tiles per supertile column (L2 reuse of W)
    const int NT = OUT_F / BN;        // 32
    const int GM = 8;
    int bid = blockIdx.x;
    int grp = bid / (GM * NT);
    int inb = bid % (GM * NT);
    int m_tile = grp * GM + (inb % GM);
    int n_tile = inb / GM;
    const int m_base = m_tile * BM;
    const int n_base = n_tile * BN;

    // gmem->smem: 128 rows x 8 chunks(16B) per tile; 256 thr x 4 iters
    const int ld_row0 = tid >> 3;            // +32/iter
    const int ld_ch   = (tid & 7) * 8;       // halves

    // ldmatrix lane address components (in halves)
    const int l7 = lane & 7;
    const int a_row = warp_m * 64 + l7 + ((lane >> 3) & 1) * 8;
    const int a_kh  = ((lane >> 4) & 1) * 8;
    const int b_row = warp_n * 32 + l7 + ((lane >> 4) & 1) * 8;
    const int b_kh  = ((lane >> 3) & 1) * 8;
    const uint32_t a_base = As_u + (uint32_t)(a_row * PITCH + a_kh) * 2;
    const uint32_t b_base = Bs_u + (uint32_t)(b_row * PITCH + b_kh) * 2;

    float acc[4][4][4];
    #pragma unroll
    for (int mi = 0; mi < 4; mi++)
        #pragma unroll
        for (int ni = 0; ni < 4; ni++)
            #pragma unroll
            for (int e = 0; e < 4; e++) acc[mi][ni][e] = 0.f;

    auto load_tile = [&](int kt, int s) {
        const __half* ga = X + (size_t)(m_base + ld_row0) * IN_F + kt * BK + ld_ch;
        const __half* gb = W + (size_t)(n_base + ld_row0) * IN_F + kt * BK + ld_ch;
        uint32_t sa = As_u + (uint32_t)(s * TILE_HALves + ld_row0 * PITCH + ld_ch) * 2;
        uint32_t sb = Bs_u + (uint32_t)(s * TILE_HALves + ld_row0 * PITCH + ld_ch) * 2;
        #pragma unroll
        for (int i = 0; i < 4; i++) {
            cp_async16(sa, ga);
            cp_async16(sb, gb);
            ga += 32 * IN_F;       gb += 32 * IN_F;
            sa += 32 * PITCH * 2;  sb += 32 * PITCH * 2;
        }
        cp_commit();
    };

    load_tile(0, 0);
    load_tile(1, 1);

    int sc = 0;
    for (int kt = 0; kt < KTILES; kt++) {
        if (kt + 1 < KTILES) cp_wait<1>(); else cp_wait<0>();
        __syncthreads();
        if (kt + 2 < KTILES) {
            int sl = sc + 2; if (sl >= STAGES) sl -= STAGES;
            load_tile(kt + 2, sl);
        }

        const uint32_t st_off = (uint32_t)(sc * TILE_HALves * 2);
        #pragma unroll
        for (int k0 = 0; k0 < BK; k0 += 16) {
            uint32_t a[4][4], b[2][4];
            #pragma unroll
            for (int mi = 0; mi < 4; mi++)
                ldsm_x4(a[mi], a_base + st_off + (uint32_t)(k0 + mi * 16 * PITCH) * 2);
            ldsm_x4(b[0], b_base + st_off + (uint32_t)(k0) * 2);
            ldsm_x4(b[1], b_base + st_off + (uint32_t)(k0 + 16 * PITCH) * 2);
            #pragma unroll
            for (int mi = 0; mi < 4; mi++) {
                mma_f16(acc[mi][0], a[mi], &b[0][0]);
                mma_f16(acc[mi][1], a[mi], &b[0][2]);
                mma_f16(acc[mi][2], a[mi], &b[1][0]);
                mma_f16(acc[mi][3], a[mi], &b[1][2]);
            }
        }
        sc = (sc + 1 == STAGES) ? 0 : sc + 1;
    }

    // epilogue: direct STG.64
    #pragma unroll
    for (int mi = 0; mi < 4; mi++) {
        int r0 = m_base + warp_m * 64 + mi * 16 + (lane >> 2);
        #pragma unroll
        for (int ni = 0; ni < 4; ni++) {
            int c = n_base + warp_n * 32 + ni * 8 + 2 * (lane & 3);
            float2 v0 = make_float2(acc[mi][ni][0], acc[mi][ni][1]);
            float2 v1 = make_float2(acc[mi][ni][2], acc[mi][ni][3]);
            *reinterpret_cast<float2*>(out + (size_t)r0 * OUT_F + c) = v0;
            *reinterpret_cast<float2*>(out + (size_t)(r0 + 8) * OUT_F + c) = v1;
        }
    }
}

// ---------------- host ----------------
extern "C" void kernel_launch(void* const* d_in, const int* in_sizes, int n_in,
                              void* d_out, int out_size) {
    const float* x    = (const float*)d_in[0];   // [8192, 4096] fp32
    const float* cent = (const float*)d_in[1];   // [256, 1] fp32
    const int*   idx  = (const int*)d_in[2];     // [4096, 4096] int32
    float* out = (float*)d_out;                  // [8192, 4096] fp32

    void* w16_ptr = nullptr; cudaGetSymbolAddress(&w16_ptr, g_w16);
    void* x16_ptr = nullptr; cudaGetSymbolAddress(&x16_ptr, g_x16);

    wdeq_kernel<<<(size_t)OUT_F * IN_F / 2048, 256>>>(cent, idx, (__half*)w16_ptr);
    xcvt_kernel<<<(size_t)MROWS * IN_F / 2048, 256>>>(x, (__half*)x16_ptr);

    cudaFuncSetAttribute(gemm_f16, cudaFuncAttributeMaxDynamicSharedMemorySize, SMEM_BYTES);
    int grid = (MROWS / BM) * (OUT_F / BN);   // 64 * 32 = 2048
    gemm_f16<<<grid, 256, SMEM_BYTES>>>((const __half*)x16_ptr, (const __half*)w16_ptr, out);
}